// round 7
// baseline (speedup 1.0000x reference)
#include <cuda_runtime.h>
#include <cuda_bf16.h>
#include <stdint.h>

// ----------------------------------------------------------------------------
// SpectralPooling via HMMA (mma.sync m16n8k16 bf16, 3-term split) GEMMs.
// y = idctn(pad(crop(dctn(x)))); axes 0,1 cancel. Per-axis operator
// B[o][i] = sum_{k<28} D32[k,o]*D64[k,i]  (32x64), applied along axes 2,3,4.
// Three stages, each GEMM [rows x 64] -> [rows x 32] against B^T; outputs are
// written "pre-transposed" so K is always contiguous and stores coalesce:
//   stage1 (SB=12): X[b][i0][i1][i2]   -> T1[b][o2][i0][i1]
//   stage2 (SB=11): T1[b][o2][i0][i1]  -> T2[b][o1][o2][i0]
//   stage3 (SB=10): T2[b][o1][o2][i0]  -> Y[b][o0][o1][o2]
// out_addr(m,c) = (m>>SB)*(32<<SB) + c*(1<<SB) + (m & ((1<<SB)-1))
// Precision: D = Ah*Bh + Ah*Bl + Al*Bh (bf16 hi/lo splits, fp32 accumulate).
// M=64 tiles (27.6 KB smem, low regs) for occupancy/latency hiding.
// ----------------------------------------------------------------------------

__device__ __nv_bfloat16 g_Bh[2048];   // B hi, row-major [o][i] (32x64)
__device__ __nv_bfloat16 g_Bl[2048];   // B lo
__device__ float g_T1[33554432];       // 128 MB scratch
__device__ float g_T2[16777216];       //  64 MB scratch

__device__ __forceinline__ uint32_t smem_u32(const void* p) {
    uint32_t a;
    asm("{ .reg .u64 t; cvta.to.shared.u64 t, %1; cvt.u32.u64 %0, t; }"
        : "=r"(a) : "l"(p));
    return a;
}

// ---------------- init: one warp per B element, lane = k-term -------------------
__global__ void init_B_kernel() {
    int gw   = (blockIdx.x * blockDim.x + threadIdx.x) >> 5;  // 0..2047
    int lane = threadIdx.x & 31;
    if (gw >= 2048) return;
    int o = gw >> 6;   // 0..31
    int i = gw & 63;   // 0..63
    float term = 0.0f;
    if (lane < 28) {
        const float s32_0 = 0.17677669529663688f;  // sqrt(1/32)
        const float s32_k = 0.25f;                 // sqrt(2/32)
        const float s64_0 = 0.125f;                // sqrt(1/64)
        const float s64_k = 0.17677669529663688f;  // sqrt(2/64)
        float a32 = (2.0f * o + 1.0f) * (float)lane / 64.0f;
        float a64 = (2.0f * i + 1.0f) * (float)lane / 128.0f;
        float d32 = ((lane == 0) ? s32_0 : s32_k) * cospif(a32);
        float d64 = ((lane == 0) ? s64_0 : s64_k) * cospif(a64);
        term = d32 * d64;
    }
    #pragma unroll
    for (int s = 16; s > 0; s >>= 1)
        term += __shfl_xor_sync(0xFFFFFFFFu, term, s);
    if (lane == 0) {
        __nv_bfloat16 h = __float2bfloat16(term);
        float lo = term - __bfloat162float(h);
        g_Bh[gw] = h;
        g_Bl[gw] = __float2bfloat16(lo);
    }
}

// ---------------- mma.sync / ldmatrix wrappers ------------------------------------
__device__ __forceinline__ void mma16816(float* d, const uint32_t* a,
                                         const uint32_t* b) {
    asm("mma.sync.aligned.m16n8k16.row.col.f32.bf16.bf16.f32 "
        "{%0,%1,%2,%3}, {%4,%5,%6,%7}, {%8,%9}, {%0,%1,%2,%3};"
        : "+f"(d[0]), "+f"(d[1]), "+f"(d[2]), "+f"(d[3])
        : "r"(a[0]), "r"(a[1]), "r"(a[2]), "r"(a[3]), "r"(b[0]), "r"(b[1]));
}

__device__ __forceinline__ void ldsm4(uint32_t* r, uint32_t addr) {
    asm volatile("ldmatrix.sync.aligned.m8n8.x4.shared.b16 {%0,%1,%2,%3}, [%4];"
                 : "=r"(r[0]), "=r"(r[1]), "=r"(r[2]), "=r"(r[3]) : "r"(addr));
}

// ---------------- stage kernel --------------------------------------------------
// A tile: 64 rows x 64 K (fp32 in -> bf16 hi/lo smem, row stride 72 bf16).
// Warp w computes rows w*16..w*16+15, all 32 output cols.
template<int SB>
__global__ __launch_bounds__(128, 6) void stage_kernel(
        const float* __restrict__ xin, float* __restrict__ xout) {
    const float* in = (SB == 12) ? xin : (SB == 11 ? (const float*)g_T1
                                                   : (const float*)g_T2);
    float* out      = (SB == 12) ? (float*)g_T1
                                 : (SB == 11 ? (float*)g_T2 : xout);
    constexpr size_t OC = (size_t)1 << SB;

    __shared__ __align__(16) __nv_bfloat16 sAh[64 * 72];   // 9 KB
    __shared__ __align__(16) __nv_bfloat16 sAl[64 * 72];   // 9 KB
    __shared__ __align__(16) __nv_bfloat16 sBh[32 * 72];   // 4.5 KB
    __shared__ __align__(16) __nv_bfloat16 sBl[32 * 72];   // 4.5 KB

    const int tid = threadIdx.x;
    const int w   = tid >> 5;
    const int lid = tid & 31;
    const int gid = lid >> 2;   // 0..7
    const int tg  = lid & 3;    // 0..3

    // ---- load B hi/lo into padded smem (row stride 144 B)
    {
        const uint32_t* bh = (const uint32_t*)g_Bh;
        const uint32_t* bl = (const uint32_t*)g_Bl;
        #pragma unroll
        for (int idx = tid; idx < 1024; idx += 128) {
            int r = idx >> 5, c2 = idx & 31;
            *(uint32_t*)&sBh[r * 72 + c2 * 2] = bh[idx];
            *(uint32_t*)&sBl[r * 72 + c2 * 2] = bl[idx];
        }
    }

    // ---- load A tile (1024 float4), split to bf16 hi/lo, padded smem
    {
        const float4* __restrict__ inp =
            (const float4*)(in + (size_t)blockIdx.x * 4096);
        #pragma unroll
        for (int j = 0; j < 8; ++j) {
            int f = j * 128 + tid;           // float4 index 0..1023
            float4 v = inp[f];
            int r = f >> 4, k4 = f & 15;
            uint32_t h01, h23, l01, l23;
            asm("cvt.rn.bf16x2.f32 %0, %1, %2;" : "=r"(h01) : "f"(v.y), "f"(v.x));
            asm("cvt.rn.bf16x2.f32 %0, %1, %2;" : "=r"(h23) : "f"(v.w), "f"(v.z));
            float hx = __uint_as_float(h01 << 16);
            float hy = __uint_as_float(h01 & 0xFFFF0000u);
            float hz = __uint_as_float(h23 << 16);
            float hw = __uint_as_float(h23 & 0xFFFF0000u);
            asm("cvt.rn.bf16x2.f32 %0, %1, %2;" : "=r"(l01)
                : "f"(v.y - hy), "f"(v.x - hx));
            asm("cvt.rn.bf16x2.f32 %0, %1, %2;" : "=r"(l23)
                : "f"(v.w - hw), "f"(v.z - hz));
            *(uint2*)&sAh[r * 72 + k4 * 4] = make_uint2(h01, h23);
            *(uint2*)&sAl[r * 72 + k4 * 4] = make_uint2(l01, l23);
        }
    }
    __syncthreads();

    // ---- per-lane ldmatrix addressing
    const int lr = lid & 7, mi = lid >> 3;
    const uint32_t uAh = smem_u32(sAh), uAl = smem_u32(sAl);
    const uint32_t uBh = smem_u32(sBh), uBl = smem_u32(sBl);
    const uint32_t aoff0 =
        (uint32_t)(w * 16 + ((mi & 1) << 3) + lr) * 144u + ((mi >> 1) << 4);
    const uint32_t boff0 =
        (uint32_t)(((mi >> 1) << 3) + lr) * 144u + ((mi & 1) << 4);

    // ---- HMMA mainloop: acc[nt][4], 16 rows x 32 cols per warp
    float acc[4][4];
    #pragma unroll
    for (int nt = 0; nt < 4; ++nt)
        #pragma unroll
        for (int q = 0; q < 4; ++q) acc[nt][q] = 0.0f;

    #pragma unroll
    for (int kk = 0; kk < 4; ++kk) {
        uint32_t ah[4], al[4];
        {
            uint32_t ao = aoff0 + (uint32_t)(kk * 32);
            ldsm4(ah, uAh + ao);
            ldsm4(al, uAl + ao);
        }
        uint32_t bh[4][2], bl[4][2];
        #pragma unroll
        for (int t = 0; t < 2; ++t) {
            uint32_t bo = boff0 + (uint32_t)(t * 16 * 144) + (uint32_t)(kk * 32);
            uint32_t rh[4], rl[4];
            ldsm4(rh, uBh + bo);
            ldsm4(rl, uBl + bo);
            bh[2 * t][0] = rh[0]; bh[2 * t][1] = rh[1];
            bh[2 * t + 1][0] = rh[2]; bh[2 * t + 1][1] = rh[3];
            bl[2 * t][0] = rl[0]; bl[2 * t][1] = rl[1];
            bl[2 * t + 1][0] = rl[2]; bl[2 * t + 1][1] = rl[3];
        }
        #pragma unroll
        for (int nt = 0; nt < 4; ++nt) {
            mma16816(acc[nt], ah, bh[nt]);   // Ah*Bh
            mma16816(acc[nt], ah, bl[nt]);   // Ah*Bl
            mma16816(acc[nt], al, bh[nt]);   // Al*Bh
        }
    }

    // ---- epilogue: CTA-wide transpose through dead sAh (64x33 fp32 = 8448 B)
    __syncthreads();                 // all warps done reading sAh/sAl
    float* ep = (float*)sAh;
    #pragma unroll
    for (int nt = 0; nt < 4; ++nt)
        #pragma unroll
        for (int q = 0; q < 4; ++q) {
            int r = w * 16 + gid + ((q >> 1) << 3);
            int c = nt * 8 + tg * 2 + (q & 1);
            ep[r * 33 + c] = acc[nt][q];
        }
    __syncthreads();

    // ---- coalesced transposed store: 16 values per thread
    float* __restrict__ ob = out
        + (size_t)(blockIdx.x >> (SB - 6)) * (OC * 32)
        + (size_t)(((uint32_t)blockIdx.x << 6) & (OC - 1));
    #pragma unroll
    for (int j = 0; j < 16; ++j) {
        int idx = j * 128 + tid;     // 0..2047
        int ml = idx & 63, c = idx >> 6;
        ob[(size_t)c * OC + (size_t)ml] = ep[ml * 33 + c];
    }
}

// ---------------- launch ---------------------------------------------------------
extern "C" void kernel_launch(void* const* d_in, const int* in_sizes, int n_in,
                              void* d_out, int out_size) {
    const float* x = (const float*)d_in[0];
    float* out = (float*)d_out;

    init_B_kernel<<<512, 128>>>();

    stage_kernel<12><<<16384, 128>>>(x, out);   // X  -> T1   (contract i2)
    stage_kernel<11><<<8192, 128>>>(x, out);    // T1 -> T2   (contract i1)
    stage_kernel<10><<<4096, 128>>>(x, out);    // T2 -> out  (contract i0)
}